// round 3
// baseline (speedup 1.0000x reference)
#include <cuda_runtime.h>

#define NB   4
#define NP   4096
#define KNN  10
#define KP   11          // K+1 including self
#define NFEAT 66

__device__ float g_Weff[6 * NFEAT];
__device__ float g_beff[6];

// Fold the 3 linear layers into a single 6x66 affine map.
// Weff = W3 @ W2 @ W1 ; beff = W3 @ (W2 @ b1 + b2) + b3
__global__ void fold_weights_kernel(const float* __restrict__ W1, const float* __restrict__ b1,
                                    const float* __restrict__ W2, const float* __restrict__ b2,
                                    const float* __restrict__ W3, const float* __restrict__ b3) {
    int t = threadIdx.x;
    if (t < NFEAT) {
        float T1[16];
        #pragma unroll
        for (int i = 0; i < 16; ++i) {
            float s = 0.f;
            #pragma unroll
            for (int j = 0; j < 32; ++j) s += W2[i * 32 + j] * W1[j * NFEAT + t];
            T1[i] = s;
        }
        #pragma unroll
        for (int c = 0; c < 6; ++c) {
            float s = 0.f;
            #pragma unroll
            for (int i = 0; i < 16; ++i) s += W3[c * 16 + i] * T1[i];
            g_Weff[c * NFEAT + t] = s;
        }
    } else if (t == NFEAT) {
        float bh[16];
        #pragma unroll
        for (int i = 0; i < 16; ++i) {
            float s = b2[i];
            #pragma unroll
            for (int j = 0; j < 32; ++j) s += W2[i * 32 + j] * b1[j];
            bh[i] = s;
        }
        #pragma unroll
        for (int c = 0; c < 6; ++c) {
            float s = b3[c];
            #pragma unroll
            for (int i = 0; i < 16; ++i) s += W3[c * 16 + i] * bh[i];
            g_beff[c] = s;
        }
    }
}

// One thread per query point. Positions of the whole batch cached in shared
// as float4(x,y,z,|p|^2). Register-resident sorted top-(K+1) list.
// Distance arithmetic pinned (no FP contraction) to match the reference's
// XLA lowering exactly:
//   sq  : ((x*x + y*y) + z*z)         separate mul/add, each rounded
//   dot : fma(z,z', fma(y,y', x*x'))  GEMM-style fma chain, acc starts at 0
//   d2  : (sq_i + sq_j) - (2*dot)     mul and sub separately rounded
__global__ void __launch_bounds__(64)
predict_kernel(const float* __restrict__ pos,
               const float* __restrict__ vel,
               const float* __restrict__ init_cfg,
               float* __restrict__ out) {
    extern __shared__ float4 tbl[];                 // [NP]
    float* Wsh = reinterpret_cast<float*>(tbl + NP); // 396
    float* bsh = Wsh + 6 * NFEAT;                    // 6

    const int b = blockIdx.y;
    const int n = blockIdx.x * 64 + threadIdx.x;
    const float* posb = pos + (size_t)b * NP * 3;

    for (int i = threadIdx.x; i < NP; i += 64) {
        float x = posb[3 * i + 0];
        float y = posb[3 * i + 1];
        float z = posb[3 * i + 2];
        // sq exactly as XLA reduce: ((x*x + y*y) + z*z), no FMA contraction
        float sq = __fadd_rn(__fadd_rn(__fmul_rn(x, x), __fmul_rn(y, y)),
                             __fmul_rn(z, z));
        tbl[i] = make_float4(x, y, z, sq);
    }
    for (int i = threadIdx.x; i < 6 * NFEAT + 6; i += 64) {
        if (i < 6 * NFEAT) Wsh[i] = g_Weff[i];
        else               bsh[i - 6 * NFEAT] = g_beff[i - 6 * NFEAT];
    }
    __syncthreads();

    const float4 q = tbl[n];

    float hd[KP];
    int   hi[KP];
    #pragma unroll
    for (int s = 0; s < KP; ++s) { hd[s] = 3.4e38f; hi[s] = 0; }

    #pragma unroll 4
    for (int j = 0; j < NP; ++j) {
        float4 p = tbl[j];
        // dot: fp32 GEMM fma chain ascending in k, acc init 0
        float dot = __fmul_rn(q.x, p.x);
        dot = __fmaf_rn(q.y, p.y, dot);
        dot = __fmaf_rn(q.z, p.z, dot);
        // d2 = (sq_i + sq_j) - 2*dot, each op rounded separately
        float S  = __fadd_rn(q.w, p.w);
        float d2 = __fsub_rn(S, __fmul_rn(2.0f, dot));
        if (d2 < hd[KP - 1]) {
            // insertion position = first slot with d2 < hd[s] (stable for ties:
            // strict < keeps earlier/lower index first, matching top_k)
            bool lt0 = d2 < hd[0];
            #pragma unroll
            for (int s = KP - 1; s >= 1; --s) {
                bool lt  = d2 < hd[s];
                bool ltp = d2 < hd[s - 1];
                float nd = lt ? (ltp ? hd[s - 1] : d2) : hd[s];
                int   ni = lt ? (ltp ? hi[s - 1] : j)  : hi[s];
                hd[s] = nd; hi[s] = ni;
            }
            if (lt0) { hd[0] = d2; hi[0] = j; }
        }
    }

    // ---- epilogue: feats @ Weff^T + beff, fused gather ----
    float acc[6];
    #pragma unroll
    for (int c = 0; c < 6; ++c) acc[c] = bsh[c];

    const float* velb = vel + (size_t)b * NP * 3;
    #pragma unroll
    for (int kk = 0; kk < KP; ++kk) {
        const int idx = hi[kk];
        // velocity features: feat indices [30 + kk*3 .. +2]
        float vx = velb[3 * idx + 0];
        float vy = velb[3 * idx + 1];
        float vz = velb[3 * idx + 2];
        const int fv = 30 + kk * 3;
        #pragma unroll
        for (int c = 0; c < 6; ++c)
            acc[c] += Wsh[c * NFEAT + fv + 0] * vx
                    + Wsh[c * NFEAT + fv + 1] * vy
                    + Wsh[c * NFEAT + fv + 2] * vz;
        if (kk >= 1) {
            // relative position features: feat indices [(kk-1)*3 .. +2]
            float4 p = tbl[idx];
            float ox = p.x - q.x, oy = p.y - q.y, oz = p.z - q.z;
            const int fo = (kk - 1) * 3;
            #pragma unroll
            for (int c = 0; c < 6; ++c)
                acc[c] += Wsh[c * NFEAT + fo + 0] * ox
                        + Wsh[c * NFEAT + fo + 1] * oy
                        + Wsh[c * NFEAT + fo + 2] * oz;
        }
    }
    // init_config features: feat indices [63..65]
    float i0 = init_cfg[b * 3 + 0];
    float i1 = init_cfg[b * 3 + 1];
    float i2 = init_cfg[b * 3 + 2];
    #pragma unroll
    for (int c = 0; c < 6; ++c)
        acc[c] += Wsh[c * NFEAT + 63] * i0
                + Wsh[c * NFEAT + 64] * i1
                + Wsh[c * NFEAT + 65] * i2;

    // residual add of position on first 3 channels
    acc[0] += q.x; acc[1] += q.y; acc[2] += q.z;

    float* o = out + ((size_t)b * NP + n) * 6;
    #pragma unroll
    for (int c = 0; c < 6; ++c) o[c] = acc[c];
}

extern "C" void kernel_launch(void* const* d_in, const int* in_sizes, int n_in,
                              void* d_out, int out_size) {
    const float* pos      = (const float*)d_in[0];
    const float* vel      = (const float*)d_in[1];
    const float* init_cfg = (const float*)d_in[2];
    const float* W1 = (const float*)d_in[3];
    const float* b1 = (const float*)d_in[4];
    const float* W2 = (const float*)d_in[5];
    const float* b2 = (const float*)d_in[6];
    const float* W3 = (const float*)d_in[7];
    const float* b3 = (const float*)d_in[8];
    float* out = (float*)d_out;

    fold_weights_kernel<<<1, 96>>>(W1, b1, W2, b2, W3, b3);

    size_t shmem = (size_t)NP * sizeof(float4) + (6 * NFEAT + 6) * sizeof(float);
    cudaFuncSetAttribute(predict_kernel,
                         cudaFuncAttributeMaxDynamicSharedMemorySize, (int)shmem);
    dim3 grid(NP / 64, NB);
    predict_kernel<<<grid, 64, shmem>>>(pos, vel, init_cfg, out);
}

// round 4
// speedup vs baseline: 1.2167x; 1.2167x over previous
#include <cuda_runtime.h>

#define NB   4
#define NP   4096
#define KNN  10
#define KP   11          // K+1 including self
#define NFEAT 66
#define QPB  64          // queries per block
#define LPQ  4           // lanes per query
#define SEG  (NP / LPQ)  // candidates per lane

__device__ float g_Weff[6 * NFEAT];
__device__ float g_beff[6];

// Fold the 3 linear layers into a single 6x66 affine map.
__global__ void fold_weights_kernel(const float* __restrict__ W1, const float* __restrict__ b1,
                                    const float* __restrict__ W2, const float* __restrict__ b2,
                                    const float* __restrict__ W3, const float* __restrict__ b3) {
    int t = threadIdx.x;
    if (t < NFEAT) {
        float T1[16];
        #pragma unroll
        for (int i = 0; i < 16; ++i) {
            float s = 0.f;
            #pragma unroll
            for (int j = 0; j < 32; ++j) s += W2[i * 32 + j] * W1[j * NFEAT + t];
            T1[i] = s;
        }
        #pragma unroll
        for (int c = 0; c < 6; ++c) {
            float s = 0.f;
            #pragma unroll
            for (int i = 0; i < 16; ++i) s += W3[c * 16 + i] * T1[i];
            g_Weff[c * NFEAT + t] = s;
        }
    } else if (t == NFEAT) {
        float bh[16];
        #pragma unroll
        for (int i = 0; i < 16; ++i) {
            float s = b2[i];
            #pragma unroll
            for (int j = 0; j < 32; ++j) s += W2[i * 32 + j] * b1[j];
            bh[i] = s;
        }
        #pragma unroll
        for (int c = 0; c < 6; ++c) {
            float s = b3[c];
            #pragma unroll
            for (int i = 0; i < 16; ++i) s += W3[c * 16 + i] * bh[i];
            g_beff[c] = s;
        }
    }
}

// 4 lanes per query, each scanning j = lane (mod 4). Register top-11 per lane,
// stable 4-way merge on (d2, j) by lane 0, which also runs the MLP epilogue.
// Distance arithmetic pinned to the reference's XLA lowering (no contraction):
//   sq  : ((x*x + y*y) + z*z)
//   dot : fma(z,z', fma(y,y', x*x'))
//   d2  : (sq_i + sq_j) - (2*dot)
__global__ void __launch_bounds__(QPB * LPQ)
predict_kernel(const float* __restrict__ pos,
               const float* __restrict__ vel,
               const float* __restrict__ init_cfg,
               float* __restrict__ out) {
    extern __shared__ float4 tbl[];                  // [NP] = 64KB
    float* Wsh    = reinterpret_cast<float*>(tbl + NP);        // 396
    float* bsh    = Wsh + 6 * NFEAT;                           // 6
    float* mbuf_d = bsh + 6;                                   // QPB*LPQ*KP
    int*   mbuf_j = reinterpret_cast<int*>(mbuf_d + QPB * LPQ * KP);

    const int tid    = threadIdx.x;
    const int qlocal = tid / LPQ;
    const int lane   = tid % LPQ;
    const int b      = blockIdx.y;
    const int n      = blockIdx.x * QPB + qlocal;
    const float* posb = pos + (size_t)b * NP * 3;

    for (int i = tid; i < NP; i += QPB * LPQ) {
        float x = posb[3 * i + 0];
        float y = posb[3 * i + 1];
        float z = posb[3 * i + 2];
        float sq = __fadd_rn(__fadd_rn(__fmul_rn(x, x), __fmul_rn(y, y)),
                             __fmul_rn(z, z));
        tbl[i] = make_float4(x, y, z, sq);
    }
    for (int i = tid; i < 6 * NFEAT + 6; i += QPB * LPQ) {
        if (i < 6 * NFEAT) Wsh[i] = g_Weff[i];
        else               bsh[i - 6 * NFEAT] = g_beff[i - 6 * NFEAT];
    }
    __syncthreads();

    const float4 q = tbl[n];

    float hd[KP];
    int   hi[KP];
    #pragma unroll
    for (int s = 0; s < KP; ++s) { hd[s] = 3.4e38f; hi[s] = 0; }

    // lane scans j = lane, lane+4, ... (each quad loads 4 consecutive float4s)
    #pragma unroll 4
    for (int i = 0; i < SEG; ++i) {
        const int j = i * LPQ + lane;
        float4 p = tbl[j];
        float dot = __fmul_rn(q.x, p.x);
        dot = __fmaf_rn(q.y, p.y, dot);
        dot = __fmaf_rn(q.z, p.z, dot);
        float S  = __fadd_rn(q.w, p.w);
        float d2 = __fsub_rn(S, __fmul_rn(2.0f, dot));
        if (d2 < hd[KP - 1]) {
            bool lt0 = d2 < hd[0];
            #pragma unroll
            for (int s = KP - 1; s >= 1; --s) {
                bool lt  = d2 < hd[s];
                bool ltp = d2 < hd[s - 1];
                float nd = lt ? (ltp ? hd[s - 1] : d2) : hd[s];
                int   ni = lt ? (ltp ? hi[s - 1] : j)  : hi[s];
                hd[s] = nd; hi[s] = ni;
            }
            if (lt0) { hd[0] = d2; hi[0] = j; }
        }
    }

    // publish per-lane sorted lists
    {
        const int base = tid * KP;
        #pragma unroll
        for (int s = 0; s < KP; ++s) { mbuf_d[base + s] = hd[s]; mbuf_j[base + s] = hi[s]; }
    }
    __syncwarp();

    if (lane == 0) {
        // stable 4-way merge: key (d2 asc, j asc) == top_k tie semantics
        int sel[KP];
        int ptr0 = 0, ptr1 = 0, ptr2 = 0, ptr3 = 0;
        const int base = qlocal * LPQ * KP;
        #pragma unroll
        for (int s = 0; s < KP; ++s) {
            float bd = 3.5e38f; int bj = 0x7fffffff; int bl = 0;
            {
                float d = mbuf_d[base + 0 * KP + ptr0]; int j = mbuf_j[base + 0 * KP + ptr0];
                if (d < bd || (d == bd && j < bj)) { bd = d; bj = j; bl = 0; }
            }
            {
                float d = mbuf_d[base + 1 * KP + ptr1]; int j = mbuf_j[base + 1 * KP + ptr1];
                if (d < bd || (d == bd && j < bj)) { bd = d; bj = j; bl = 1; }
            }
            {
                float d = mbuf_d[base + 2 * KP + ptr2]; int j = mbuf_j[base + 2 * KP + ptr2];
                if (d < bd || (d == bd && j < bj)) { bd = d; bj = j; bl = 2; }
            }
            {
                float d = mbuf_d[base + 3 * KP + ptr3]; int j = mbuf_j[base + 3 * KP + ptr3];
                if (d < bd || (d == bd && j < bj)) { bd = d; bj = j; bl = 3; }
            }
            sel[s] = bj;
            if      (bl == 0) ++ptr0;
            else if (bl == 1) ++ptr1;
            else if (bl == 2) ++ptr2;
            else              ++ptr3;
        }

        // ---- epilogue: feats @ Weff^T + beff, fused gather ----
        float acc[6];
        #pragma unroll
        for (int c = 0; c < 6; ++c) acc[c] = bsh[c];

        const float* velb = vel + (size_t)b * NP * 3;
        #pragma unroll
        for (int kk = 0; kk < KP; ++kk) {
            const int idx = sel[kk];
            float vx = velb[3 * idx + 0];
            float vy = velb[3 * idx + 1];
            float vz = velb[3 * idx + 2];
            const int fv = 30 + kk * 3;
            #pragma unroll
            for (int c = 0; c < 6; ++c)
                acc[c] += Wsh[c * NFEAT + fv + 0] * vx
                        + Wsh[c * NFEAT + fv + 1] * vy
                        + Wsh[c * NFEAT + fv + 2] * vz;
            if (kk >= 1) {
                float4 p = tbl[idx];
                float ox = p.x - q.x, oy = p.y - q.y, oz = p.z - q.z;
                const int fo = (kk - 1) * 3;
                #pragma unroll
                for (int c = 0; c < 6; ++c)
                    acc[c] += Wsh[c * NFEAT + fo + 0] * ox
                            + Wsh[c * NFEAT + fo + 1] * oy
                            + Wsh[c * NFEAT + fo + 2] * oz;
            }
        }
        float i0 = init_cfg[b * 3 + 0];
        float i1 = init_cfg[b * 3 + 1];
        float i2 = init_cfg[b * 3 + 2];
        #pragma unroll
        for (int c = 0; c < 6; ++c)
            acc[c] += Wsh[c * NFEAT + 63] * i0
                    + Wsh[c * NFEAT + 64] * i1
                    + Wsh[c * NFEAT + 65] * i2;

        acc[0] += q.x; acc[1] += q.y; acc[2] += q.z;

        float* o = out + ((size_t)b * NP + n) * 6;
        #pragma unroll
        for (int c = 0; c < 6; ++c) o[c] = acc[c];
    }
}

extern "C" void kernel_launch(void* const* d_in, const int* in_sizes, int n_in,
                              void* d_out, int out_size) {
    const float* pos      = (const float*)d_in[0];
    const float* vel      = (const float*)d_in[1];
    const float* init_cfg = (const float*)d_in[2];
    const float* W1 = (const float*)d_in[3];
    const float* b1 = (const float*)d_in[4];
    const float* W2 = (const float*)d_in[5];
    const float* b2 = (const float*)d_in[6];
    const float* W3 = (const float*)d_in[7];
    const float* b3 = (const float*)d_in[8];
    float* out = (float*)d_out;

    fold_weights_kernel<<<1, 96>>>(W1, b1, W2, b2, W3, b3);

    size_t shmem = (size_t)NP * sizeof(float4)
                 + (6 * NFEAT + 6) * sizeof(float)
                 + (size_t)QPB * LPQ * KP * (sizeof(float) + sizeof(int));
    cudaFuncSetAttribute(predict_kernel,
                         cudaFuncAttributeMaxDynamicSharedMemorySize, (int)shmem);
    dim3 grid(NP / QPB, NB);
    predict_kernel<<<grid, QPB * LPQ, shmem>>>(pos, vel, init_cfg, out);
}